// round 1
// baseline (speedup 1.0000x reference)
#include <cuda_runtime.h>

#define Bb 4
#define Nn 1024
#define BN 4096
#define Ff 128
#define Rr 16
#define Ee 65536
#define NSTEPS 2

// ---------------- scratch (device globals; no runtime allocation) ----------------
__device__ float g_agg1[2][BN * Ff];          // psi1 neighbor aggregation (s, t)
__device__ float g_h[2][BN * Ff];             // h_s, h_t
__device__ float g_Shat[(size_t)Bb * Nn * Nn]; // 16 MB logits
__device__ float g_m[BN];                     // row max
__device__ float g_invZ[BN];                  // 1/row sum-exp
__device__ float g_rt[BN * Rr];               // r_t
__device__ float g_aggR[BN * Rr];             // psi2 aggregation scratch
__device__ float g_As[NSTEPS][BN * Rr];       // A_s = o_s@Wm1 + bm1 per step
__device__ float g_Bt[BN * Rr];               // B_t = o_t@Wm1

// ---------------- zero kernels ----------------
__global__ void k_zero_agg1() {
    int i = blockIdx.x * blockDim.x + threadIdx.x;      // 262144 float4
    ((float4*)g_agg1)[i] = make_float4(0.f, 0.f, 0.f, 0.f);
}

__global__ void k_zeroR(int which) {                    // 16384 float4
    float* p = which ? g_rt : g_aggR;
    int i = blockIdx.x * blockDim.x + threadIdx.x;
    ((float4*)p)[i] = make_float4(0.f, 0.f, 0.f, 0.f);
}

// ---------------- psi1 aggregation: agg[dst] += x[src] over edges ----------------
__global__ void k_scatter128(const float* __restrict__ xs, const float* __restrict__ xt,
                             const int* __restrict__ eis, const int* __restrict__ eit) {
    int g = blockIdx.y;
    const float* x = g ? xt : xs;
    const int* ei = g ? eit : eis;
    float* agg = g_agg1[g];
    int idx = blockIdx.x * blockDim.x + threadIdx.x;    // < E*F
    int e = idx >> 7;
    int f = idx & 127;
    int src = ei[e];
    int dst = ei[Ee + e];
    atomicAdd(&agg[dst * Ff + f], x[src * Ff + f]);
}

// ---------------- psi1 GEMM: h = relu(x@Ws + agg@Wn + b1) ----------------
// BM=32 rows/block, 256 threads (tx=0..31 -> 4 cols, ty=0..7 -> 4 rows), K=128 per phase
__global__ __launch_bounds__(256) void k_psi1(
    const float* __restrict__ xs, const float* __restrict__ xt,
    const float* __restrict__ Ws, const float* __restrict__ Wn,
    const float* __restrict__ bias) {
    __shared__ float sA[32][36];
    __shared__ float sW[32][128];

    int g = blockIdx.y;
    const float* x = g ? xt : xs;
    const float* agg = g_agg1[g];
    float* h = g_h[g];

    int tid = threadIdx.x;
    int tx = tid & 31;          // col group: cols 4*tx..4*tx+3
    int ty = tid >> 5;          // row group: rows 4*ty..4*ty+3
    int row0 = blockIdx.x * 32;

    float acc[4][4];
#pragma unroll
    for (int i = 0; i < 4; ++i)
#pragma unroll
        for (int j = 0; j < 4; ++j) acc[i][j] = 0.f;

#pragma unroll
    for (int phase = 0; phase < 2; ++phase) {
        const float* A = phase ? agg : x;
        const float* W = phase ? Wn : Ws;
        for (int kc = 0; kc < Ff; kc += 32) {
            __syncthreads();
            {   // A tile 32x32
                int r = tid >> 3, kq = tid & 7;
                float4 v = *(const float4*)&A[(size_t)(row0 + r) * Ff + kc + 4 * kq];
                *(float4*)&sA[r][4 * kq] = v;
            }
            {   // W tile 32x128
                int j4 = tid & 31, kk0 = tid >> 5;
#pragma unroll
                for (int i = 0; i < 4; ++i) {
                    int kk = kk0 + 8 * i;
                    *(float4*)&sW[kk][4 * j4] =
                        *(const float4*)&W[(size_t)(kc + kk) * Ff + 4 * j4];
                }
            }
            __syncthreads();
#pragma unroll
            for (int k = 0; k < 32; ++k) {
                float4 w = *(float4*)&sW[k][4 * tx];
                float a0 = sA[4 * ty + 0][k];
                float a1 = sA[4 * ty + 1][k];
                float a2 = sA[4 * ty + 2][k];
                float a3 = sA[4 * ty + 3][k];
                acc[0][0] += a0 * w.x; acc[0][1] += a0 * w.y; acc[0][2] += a0 * w.z; acc[0][3] += a0 * w.w;
                acc[1][0] += a1 * w.x; acc[1][1] += a1 * w.y; acc[1][2] += a1 * w.z; acc[1][3] += a1 * w.w;
                acc[2][0] += a2 * w.x; acc[2][1] += a2 * w.y; acc[2][2] += a2 * w.z; acc[2][3] += a2 * w.w;
                acc[3][0] += a3 * w.x; acc[3][1] += a3 * w.y; acc[3][2] += a3 * w.z; acc[3][3] += a3 * w.w;
            }
        }
    }
    float4 bv = *(const float4*)&bias[4 * tx];
#pragma unroll
    for (int i = 0; i < 4; ++i) {
        float4 o;
        o.x = fmaxf(acc[i][0] + bv.x, 0.f);
        o.y = fmaxf(acc[i][1] + bv.y, 0.f);
        o.z = fmaxf(acc[i][2] + bv.z, 0.f);
        o.w = fmaxf(acc[i][3] + bv.w, 0.f);
        *(float4*)&h[(size_t)(row0 + 4 * ty + i) * Ff + 4 * tx] = o;
    }
}

// ---------------- S_hat = h_s @ h_t^T per batch ----------------
// BM=128 (s), BN=64 (t), BK=16; 256 threads; micro 8x4
__global__ __launch_bounds__(256) void k_shat() {
    __shared__ float sA[128][20];
    __shared__ float sB[64][20];

    int b = blockIdx.z;
    int t0 = blockIdx.x * 64;
    int s0 = blockIdx.y * 128;
    const float* hs = g_h[0] + (size_t)b * Nn * Ff;
    const float* ht = g_h[1] + (size_t)b * Nn * Ff;

    int tid = threadIdx.x;
    int tx = tid & 15;     // cols 4*tx
    int ty = tid >> 4;     // rows 8*ty

    float acc[8][4];
#pragma unroll
    for (int i = 0; i < 8; ++i)
#pragma unroll
        for (int j = 0; j < 4; ++j) acc[i][j] = 0.f;

    for (int kc = 0; kc < Ff; kc += 16) {
        __syncthreads();
        {
            int m = tid >> 2, kq = tid & 3;
            *(float4*)&sA[m][4 * kq] =
                *(const float4*)&hs[(size_t)(s0 + m) * Ff + kc + 4 * kq];
            *(float4*)&sA[m + 64][4 * kq] =
                *(const float4*)&hs[(size_t)(s0 + m + 64) * Ff + kc + 4 * kq];
            *(float4*)&sB[m][4 * kq] =
                *(const float4*)&ht[(size_t)(t0 + m) * Ff + kc + 4 * kq];
        }
        __syncthreads();
#pragma unroll
        for (int k = 0; k < 16; ++k) {
            float bb[4];
#pragma unroll
            for (int j = 0; j < 4; ++j) bb[j] = sB[4 * tx + j][k];
#pragma unroll
            for (int i = 0; i < 8; ++i) {
                float a = sA[8 * ty + i][k];
#pragma unroll
                for (int j = 0; j < 4; ++j) acc[i][j] += a * bb[j];
            }
        }
    }
#pragma unroll
    for (int i = 0; i < 8; ++i) {
        float4 o = make_float4(acc[i][0], acc[i][1], acc[i][2], acc[i][3]);
        *(float4*)&g_Shat[((size_t)(b * Nn + s0 + 8 * ty + i)) * Nn + t0 + 4 * tx] = o;
    }
}

// ---------------- row stats: m, 1/Z ----------------
__global__ __launch_bounds__(256) void k_stats() {
    int row = blockIdx.x;
    int tid = threadIdx.x;
    const float4* p = (const float4*)(g_Shat + (size_t)row * Nn);
    float4 v = p[tid];
    float m = fmaxf(fmaxf(v.x, v.y), fmaxf(v.z, v.w));
#pragma unroll
    for (int o = 16; o > 0; o >>= 1) m = fmaxf(m, __shfl_xor_sync(0xffffffffu, m, o));
    __shared__ float smax[8];
    __shared__ float ssum[8];
    int wid = tid >> 5, lane = tid & 31;
    if (lane == 0) smax[wid] = m;
    __syncthreads();
    if (tid == 0) {
        float mm = smax[0];
#pragma unroll
        for (int i = 1; i < 8; ++i) mm = fmaxf(mm, smax[i]);
        smax[0] = mm;
    }
    __syncthreads();
    m = smax[0];
    float s = __expf(v.x - m) + __expf(v.y - m) + __expf(v.z - m) + __expf(v.w - m);
#pragma unroll
    for (int o = 16; o > 0; o >>= 1) s += __shfl_xor_sync(0xffffffffu, s, o);
    if (lane == 0) ssum[wid] = s;
    __syncthreads();
    if (tid == 0) {
        float ss = 0.f;
#pragma unroll
        for (int i = 0; i < 8; ++i) ss += ssum[i];
        g_m[row] = m;
        g_invZ[row] = 1.0f / ss;
    }
}

// ---------------- softmax write-out ----------------
__global__ __launch_bounds__(256) void k_smout(float* __restrict__ out) {
    size_t i4 = (size_t)blockIdx.x * blockDim.x + threadIdx.x;  // over 1M float4
    float4 v = ((const float4*)g_Shat)[i4];
    int row = (int)(i4 >> 8);                                   // i4*4/1024
    float m = g_m[row], iz = g_invZ[row];
    float4 o;
    o.x = __expf(v.x - m) * iz;
    o.y = __expf(v.y - m) * iz;
    o.z = __expf(v.z - m) * iz;
    o.w = __expf(v.w - m) * iz;
    ((float4*)out)[i4] = o;
}

// ---------------- r_t = softmax(S_hat)^T @ r_s ----------------
// grid (t_chunks=8, s_chunks=8, B), 128 threads
__global__ __launch_bounds__(128) void k_rt(const float* __restrict__ rs) {
    __shared__ float s_rs[128][Rr];
    __shared__ float s_m[128];
    __shared__ float s_iz[128];
    int b = blockIdx.z;
    int t0 = blockIdx.x * 128;
    int s0 = blockIdx.y * 128;
    int tid = threadIdx.x;
#pragma unroll
    for (int i = 0; i < 16; ++i) {
        int lin = tid + 128 * i;
        int r = lin >> 4, c = lin & 15;
        s_rs[r][c] = rs[((size_t)(b * Nn + s0 + r)) * Rr + c];
    }
    s_m[tid] = g_m[b * Nn + s0 + tid];
    s_iz[tid] = g_invZ[b * Nn + s0 + tid];
    __syncthreads();

    int t = t0 + tid;
    float acc[Rr];
#pragma unroll
    for (int r = 0; r < Rr; ++r) acc[r] = 0.f;
    const float* sp = g_Shat + ((size_t)(b * Nn + s0)) * Nn + t;
#pragma unroll 4
    for (int s = 0; s < 128; ++s) {
        float w = __expf(sp[(size_t)s * Nn] - s_m[s]) * s_iz[s];
#pragma unroll
        for (int r = 0; r < Rr; ++r) acc[r] += w * s_rs[s][r];
    }
    float* rt = g_rt + (size_t)(b * Nn + t) * Rr;
#pragma unroll
    for (int r = 0; r < Rr; ++r) atomicAdd(&rt[r], acc[r]);
}

// ---------------- psi2 aggregation: aggR[dst] += src[srcnode] (R=16) ----------------
__global__ void k_scatter16(int src_is_rt, const float* __restrict__ rext,
                            const int* __restrict__ ei) {
    int idx = blockIdx.x * blockDim.x + threadIdx.x;   // < E*R
    int e = idx >> 4;
    int f = idx & 15;
    const float* src = src_is_rt ? g_rt : rext;
    atomicAdd(&g_aggR[ei[Ee + e] * Rr + f], src[ei[e] * Rr + f]);
}

// ---------------- psi2 + Wm1 projection fused ----------------
// o = relu(r@W2s + aggR@W2n + b2); out = o@Wm1 (+bm1)
__global__ __launch_bounds__(256) void k_psi2(
    int src_is_rt, const float* __restrict__ rext,
    const float* __restrict__ W2s, const float* __restrict__ W2n,
    const float* __restrict__ b2v, const float* __restrict__ Wm1,
    int use_bm1, const float* __restrict__ bm1v, int out_is_B, int step) {
    __shared__ float sr[16][17], sg[16][17], so[16][17];
    __shared__ float sWs[256], sWn[256], sWm[256];
    int tid = threadIdx.x;
    int r = tid >> 4, j = tid & 15;
    int row0 = blockIdx.x * 16;
    const float* src = src_is_rt ? g_rt : rext;
    sr[r][j] = src[(size_t)(row0 + r) * Rr + j];
    sg[r][j] = g_aggR[(size_t)(row0 + r) * Rr + j];
    sWs[tid] = W2s[tid];
    sWn[tid] = W2n[tid];
    sWm[tid] = Wm1[tid];
    __syncthreads();
    float acc = b2v[j];
#pragma unroll
    for (int k = 0; k < 16; ++k)
        acc += sr[r][k] * sWs[k * 16 + j] + sg[r][k] * sWn[k * 16 + j];
    so[r][j] = fmaxf(acc, 0.f);
    __syncthreads();
    float a2 = use_bm1 ? bm1v[j] : 0.f;
#pragma unroll
    for (int k = 0; k < 16; ++k) a2 += so[r][k] * sWm[k * 16 + j];
    float* dst = out_is_B ? g_Bt : g_As[step];
    dst[(size_t)(row0 + r) * Rr + j] = a2;
}

// ---------------- S_hat += sum_k relu(A_s[s,k]-B_t[t,k])*Wm2[k] + bm2 ----------------
// grid (t_chunks=4, s_tiles=64, B), 256 threads
__global__ __launch_bounds__(256) void k_upd(int step, const float* __restrict__ Wm2,
                                             const float* __restrict__ bm2v) {
    __shared__ float sA[16][16];
    __shared__ float swm[16];
    int b = blockIdx.z;
    int s0 = blockIdx.y * 16;
    int t0 = blockIdx.x * 256;
    int tid = threadIdx.x;
    sA[tid >> 4][tid & 15] = g_As[step][(size_t)(b * Nn + s0 + (tid >> 4)) * Rr + (tid & 15)];
    if (tid < 16) swm[tid] = Wm2[tid];
    float bb = bm2v[0];
    int t = t0 + tid;
    float Bk[16];
    const float4* bp = (const float4*)&g_Bt[(size_t)(b * Nn + t) * Rr];
    float4 b0 = bp[0], b1 = bp[1], b2 = bp[2], b3 = bp[3];
    Bk[0] = b0.x; Bk[1] = b0.y; Bk[2] = b0.z; Bk[3] = b0.w;
    Bk[4] = b1.x; Bk[5] = b1.y; Bk[6] = b1.z; Bk[7] = b1.w;
    Bk[8] = b2.x; Bk[9] = b2.y; Bk[10] = b2.z; Bk[11] = b2.w;
    Bk[12] = b3.x; Bk[13] = b3.y; Bk[14] = b3.z; Bk[15] = b3.w;
    __syncthreads();
    float* shp = g_Shat + ((size_t)(b * Nn + s0)) * Nn + t;
#pragma unroll
    for (int s = 0; s < 16; ++s) {
        float acc = bb;
#pragma unroll
        for (int k = 0; k < 16; ++k)
            acc += fmaxf(sA[s][k] - Bk[k], 0.f) * swm[k];
        shp[(size_t)s * Nn] += acc;
    }
}

// ---------------- host orchestration ----------------
extern "C" void kernel_launch(void* const* d_in, const int* in_sizes, int n_in,
                              void* d_out, int out_size) {
    const float* x_s   = (const float*)d_in[0];
    const int*   ei_s  = (const int*)d_in[1];
    const float* x_t   = (const float*)d_in[2];
    const int*   ei_t  = (const int*)d_in[3];
    const float* W1s   = (const float*)d_in[4];
    const float* W1n   = (const float*)d_in[5];
    const float* b1    = (const float*)d_in[6];
    const float* W2s   = (const float*)d_in[7];
    const float* W2n   = (const float*)d_in[8];
    const float* b2v   = (const float*)d_in[9];
    const float* Wm1   = (const float*)d_in[10];
    const float* bm1v  = (const float*)d_in[11];
    const float* Wm2   = (const float*)d_in[12];
    const float* bm2v  = (const float*)d_in[13];
    const float* rsteps = (const float*)d_in[14];
    float* out = (float*)d_out;

    // psi1
    k_zero_agg1<<<1024, 256>>>();
    k_scatter128<<<dim3(Ee * Ff / 256, 2), 256>>>(x_s, x_t, ei_s, ei_t);
    k_psi1<<<dim3(BN / 32, 2), 256>>>(x_s, x_t, W1s, W1n, b1);

    // S_hat + initial stats + S_0
    k_shat<<<dim3(Nn / 64, Nn / 128, Bb), 256>>>();
    k_stats<<<BN, 256>>>();
    k_smout<<<4096, 256>>>(out);

    for (int step = 0; step < NSTEPS; ++step) {
        const float* rs = rsteps + (size_t)step * Bb * Nn * Rr;

        // o_s path -> A_s[step]  (uses graph s, input r_s)
        k_zeroR<<<64, 256>>>(0);
        k_scatter16<<<Ee * Rr / 256, 256>>>(0, rs, ei_s);
        k_psi2<<<BN / 16, 256>>>(0, rs, W2s, W2n, b2v, Wm1, 1, bm1v, 0, step);

        // r_t = softmax(S_hat)^T @ r_s  (uses current stats)
        k_zeroR<<<64, 256>>>(1);
        k_rt<<<dim3(8, 8, Bb), 128>>>(rs);

        // o_t path -> B_t  (graph t, r_t)
        k_zeroR<<<64, 256>>>(0);
        k_scatter16<<<Ee * Rr / 256, 256>>>(1, rs, ei_t);
        k_psi2<<<BN / 16, 256>>>(1, rs, W2s, W2n, b2v, Wm1, 0, bm1v, 1, step);

        // S_hat += upd ; refresh stats
        k_upd<<<dim3(4, 64, Bb), 256>>>(step, Wm2, bm2v);
        k_stats<<<BN, 256>>>();
    }

    // S_L
    k_smout<<<4096, 256>>>(out + (size_t)Bb * Nn * Nn);
}